// round 12
// baseline (speedup 1.0000x reference)
#include <cuda_runtime.h>
#include <cuda_fp16.h>
#include <math.h>
#include <stdint.h>

#define Bq 128
#define Uq 256
#define NG 1280

// ---------------- scratch (static device globals) ----------------------------
__device__ float g_gsum[Bq * NG];
__device__ float g_c  [Bq * Uq];
__device__ float g_fre[Bq * Uq];
__device__ float g_ste[Bq * Uq];
__device__ float g_cos[Bq * Uq];
__device__ float g_sin[Bq * Uq];
__device__ __half g_Ah[(size_t)Uq * Bq * Uq];  // [k][b][u], 16.8MB
__device__ __half g_xh[Bq * Uq];
__device__ __half g_zh[Bq * Uq];

__device__ __forceinline__ float hsig(float v) {
    return fminf(fmaxf(0.2f * v + 0.5f, 0.0f), 1.0f);
}

// ---------------- PTX helpers (sm_80-level only) ------------------------------
__device__ __forceinline__ uint32_t smem_u32(const void* p) {
    uint32_t a;
    asm("{ .reg .u64 t; cvta.to.shared.u64 t, %1; cvt.u32.u64 %0, t; }" : "=r"(a) : "l"(p));
    return a;
}
__device__ __forceinline__ uint32_t packh(float lo, float hi) {
    __half2 h = __floats2half2_rn(lo, hi);
    return *(uint32_t*)&h;
}
__device__ __forceinline__ void sts128(uint32_t a, uint32_t r0, uint32_t r1, uint32_t r2, uint32_t r3) {
    asm volatile("st.shared.v4.b32 [%0], {%1,%2,%3,%4};"
                 :: "r"(a), "r"(r0), "r"(r1), "r"(r2), "r"(r3) : "memory");
}
__device__ __forceinline__ void cpa16(uint32_t dst, const void* src) {
    asm volatile("cp.async.cg.shared.global [%0], [%1], 16;" :: "r"(dst), "l"(src) : "memory");
}
__device__ __forceinline__ void cpa_commit() {
    asm volatile("cp.async.commit_group;" ::: "memory");
}
__device__ __forceinline__ void cpa_wait0() {
    asm volatile("cp.async.wait_group 0;" ::: "memory");
}
__device__ __forceinline__ void cpa_wait1() {
    asm volatile("cp.async.wait_group 1;" ::: "memory");
}
__device__ __forceinline__ void ldsm4(uint32_t* r, uint32_t addr) {
    asm volatile("ldmatrix.sync.aligned.m8n8.x4.shared.b16 {%0,%1,%2,%3}, [%4];"
                 : "=r"(r[0]), "=r"(r[1]), "=r"(r[2]), "=r"(r[3]) : "r"(addr));
}
__device__ __forceinline__ void ldsm4t(uint32_t* r, uint32_t addr) {
    asm volatile("ldmatrix.sync.aligned.m8n8.x4.trans.shared.b16 {%0,%1,%2,%3}, [%4];"
                 : "=r"(r[0]), "=r"(r[1]), "=r"(r[2]), "=r"(r[3]) : "r"(addr));
}
__device__ __forceinline__ void mma_f16(float* c, const uint32_t* a, const uint32_t* b) {
    asm volatile(
        "mma.sync.aligned.m16n8k16.row.col.f32.f16.f16.f32 "
        "{%0,%1,%2,%3}, {%4,%5,%6,%7}, {%8,%9}, {%0,%1,%2,%3};"
        : "+f"(c[0]), "+f"(c[1]), "+f"(c[2]), "+f"(c[3])
        : "r"(a[0]), "r"(a[1]), "r"(a[2]), "r"(a[3]), "r"(b[0]), "r"(b[1]));
}

// ============================================================================
// Kernel 1: g_gsum = x @ kernel + z_prev @ recur_k + bias.  32x64 tiles.
// ============================================================================
__global__ __launch_bounds__(256) void k_gates_gemm(
    const float* __restrict__ x, const float* __restrict__ z_prev,
    const float* __restrict__ kern, const float* __restrict__ recur,
    const float* __restrict__ bias)
{
    __shared__ float sX[32][33];
    __shared__ float sW[32][68];
    const int tid = threadIdx.x;
    const int j0 = blockIdx.x * 64, b0 = blockIdx.y * 32;
    const int rg = tid >> 4, cg = tid & 15;
    float acc[2][4];
#pragma unroll
    for (int i = 0; i < 2; i++)
#pragma unroll
        for (int j = 0; j < 4; j++) acc[i][j] = 0.f;

#pragma unroll
    for (int pass = 0; pass < 2; pass++) {
        const float* L = pass ? z_prev : x;
        const float* W = pass ? recur : kern;
        for (int d0 = 0; d0 < 256; d0 += 32) {
            {
                const int lb = tid >> 3, lu = (tid & 7) * 4;
                float4 v = *(const float4*)&L[(b0 + lb) * 256 + d0 + lu];
                sX[lu][lb] = v.x; sX[lu + 1][lb] = v.y;
                sX[lu + 2][lb] = v.z; sX[lu + 3][lb] = v.w;
            }
#pragma unroll
            for (int i2 = 0; i2 < 2; i2++) {
                const int wu = (tid >> 4) + i2 * 16, wc = (tid & 15) * 4;
                *(float4*)&sW[wu][wc] = *(const float4*)&W[(d0 + wu) * NG + j0 + wc];
            }
            __syncthreads();
#pragma unroll
            for (int kk = 0; kk < 32; kk++) {
                float a0 = sX[kk][rg * 2], a1 = sX[kk][rg * 2 + 1];
                float bb[4];
#pragma unroll
                for (int j = 0; j < 4; j++) bb[j] = sW[kk][cg * 4 + j];
#pragma unroll
                for (int j = 0; j < 4; j++) { acc[0][j] += a0 * bb[j]; acc[1][j] += a1 * bb[j]; }
            }
            __syncthreads();
        }
    }
#pragma unroll
    for (int i = 0; i < 2; i++) {
        const int b = b0 + rg * 2 + i;
#pragma unroll
        for (int j = 0; j < 4; j++) {
            const int jj = j0 + cg * 4 + j;
            g_gsum[b * NG + jj] = acc[i][j] + bias[jj];
        }
    }
}

// ============================================================================
// Kernel 2: elementwise gates + omega out + cos/sin + fp16 copies of x, z_prev
// ============================================================================
__global__ __launch_bounds__(256) void k_gates_ew(
    const float* __restrict__ x, const float* __restrict__ z_prev,
    const float* __restrict__ omg_prev, const float* __restrict__ t,
    float* __restrict__ out_omg)
{
    const int idx = blockIdx.x * blockDim.x + threadIdx.x;
    const int b = idx >> 8, u = idx & 255;
    const float* g = &g_gsum[b * NG];
    const float i_g = hsig(g[u]);
    const float fre = hsig(g[Uq + u]);
    const float ste = hsig(g[2 * Uq + u]);
    const float gg  = tanhf(g[3 * Uq + u]);
    g_c[idx] = i_g * gg; g_fre[idx] = fre; g_ste[idx] = ste;
    const float th = omg_prev[idx] * t[b];
    g_cos[idx] = cosf(th); g_sin[idx] = sinf(th);
    out_omg[idx] = g[4 * Uq + u];
    g_xh[idx] = __float2half_rn(x[idx]);
    g_zh[idx] = __float2half_rn(z_prev[idx]);
}

// ============================================================================
// Kernel 3: Re/Im update + A = sqrt(Re^2+Im^2) -> g_Ah [k][b][u] (fp16)
// ============================================================================
__global__ __launch_bounds__(256) void k_reim(
    const float* __restrict__ Re_prev, const float* __restrict__ Im_prev,
    float* __restrict__ Im_out, float* __restrict__ Re_out)
{
    __shared__ float sA[64][65];
    const int b = blockIdx.z, i0 = blockIdx.y * 64, j0 = blockIdx.x * 64;
    const int t16 = threadIdx.x & 15, tr = threadIdx.x >> 4;
    const int j4 = t16 * 4;

    const float4 fre4 = *(const float4*)&g_fre[b * Uq + j0 + j4];
    const float4 cos4 = *(const float4*)&g_cos[b * Uq + j0 + j4];
    const float4 sin4 = *(const float4*)&g_sin[b * Uq + j0 + j4];
    const float frev[4] = {fre4.x, fre4.y, fre4.z, fre4.w};
    const float cosv[4] = {cos4.x, cos4.y, cos4.z, cos4.w};
    const float sinv[4] = {sin4.x, sin4.y, sin4.z, sin4.w};

#pragma unroll
    for (int r = 0; r < 4; r++) {
        const int i = tr + r * 16;
        const float ste_i = g_ste[b * Uq + i0 + i];
        const float ci    = g_c  [b * Uq + i0 + i];
        const size_t idx = ((size_t)b * Uq + (i0 + i)) * Uq + j0 + j4;
        const float4 rp = *(const float4*)&Re_prev[idx];
        const float4 ip = *(const float4*)&Im_prev[idx];
        const float rpv[4] = {rp.x, rp.y, rp.z, rp.w};
        const float ipv[4] = {ip.x, ip.y, ip.z, ip.w};
        float rev[4], imv[4];
#pragma unroll
        for (int q = 0; q < 4; q++) {
            const float f = ste_i * frev[q];
            rev[q] = f * rpv[q] + ci * cosv[q];
            imv[q] = f * ipv[q] + ci * sinv[q];
            sA[i][j4 + q] = sqrtf(rev[q] * rev[q] + imv[q] * imv[q]);
        }
        *(float4*)&Re_out[idx] = make_float4(rev[0], rev[1], rev[2], rev[3]);
        *(float4*)&Im_out[idx] = make_float4(imv[0], imv[1], imv[2], imv[3]);
    }
    __syncthreads();
#pragma unroll
    for (int r = 0; r < 4; r++) {
        const int j = tr + r * 16;
        const int i4 = t16 * 4;
        __half2 h0 = __floats2half2_rn(sA[i4][j],     sA[i4 + 1][j]);
        __half2 h1 = __floats2half2_rn(sA[i4 + 2][j], sA[i4 + 3][j]);
        uint2 v = make_uint2(*(uint32_t*)&h0, *(uint32_t*)&h1);
        *(uint2*)&g_Ah[((size_t)(j0 + j) * 128 + b) * 256 + i0 + i4] = v;
    }
}

// ============================================================================
// Kernel 4: per-k fused GEMMs via mma.sync fp16 -- 128x32 block tile, 3 CTA/SM.
// Grid (8 vq, 256 k). 256 threads, warps 4(M)x2(N), warp tile 32x16.
// Chunks of K=64:  c 0-3:  A @ [U_o | W_z]  -> acc_o, acc_z
//                  c 4-7:  x @ W_o          -> acc_o
//                  c 8-11: z_prev @ V_o     -> acc_o
// Distance-2 pipeline: 3 LHS cp.async slots, 2 B-pair slots (LDG->cvt->STS).
// ============================================================================
#define LDA 144                 // 64 fp16 (128B) + 16B pad
#define LDB_H 80                // 32 fp16 (64B) + 16B pad
#define L_BYTES (128*LDA)       // 18432 per LHS slot
#define B_BYTES_H (64*LDB_H)    // 5120 per B tile
#define BP_BYTES (2*B_BYTES_H)  // 10240 per B pair slot
#define SMEM_TOT (3*L_BYTES + 2*BP_BYTES)   // 75776

__global__ __launch_bounds__(256, 3) void k_freq_mma(
    const float* __restrict__ freq_k, const float* __restrict__ freq_ki,
    const float* __restrict__ freqb, float* __restrict__ z_out)
{
    extern __shared__ char smem[];
    const uint32_t sbase = smem_u32(smem);
    const int tid = threadIdx.x, l = tid & 31, w = tid >> 5;
    const int wm = w & 3, wn = w >> 2;
    const int k = blockIdx.y, v0 = blockIdx.x * 32;

    const uint32_t L0 = sbase, L1 = sbase + L_BYTES, L2 = sbase + 2 * L_BYTES;
    const uint32_t P0 = sbase + 3 * L_BYTES, P1 = P0 + BP_BYTES;

    float acc_o[2][2][4], acc_z[2][2][4];
#pragma unroll
    for (int i = 0; i < 16; i++) { ((float*)acc_o)[i] = 0.f; ((float*)acc_z)[i] = 0.f; }

    const uint32_t a_base = (uint32_t)((wm * 32 + (l & 15)) * LDA + (l >> 4) * 16);
    const uint32_t b_base = (uint32_t)((l & 15) * LDB_H + wn * 32 + (l >> 4) * 16);

    // B staging regs: 2 float4 per tile, 2 tiles in A-phase
    float4 hb[4];

    // per-thread B load coords: 4 threads/row, 8 floats each
    const int br = tid >> 2;        // row 0..63
    const int bg = tid & 3;         // col group (8 floats)

    auto load_lhs = [&](int c, uint32_t dst) {
        const __half* ls;
        if (c < 4)      ls = g_Ah + (size_t)k * 32768 + c * 64;
        else if (c < 8) ls = g_xh + (c - 4) * 64;
        else            ls = g_zh + (c - 8) * 64;
#pragma unroll
        for (int i = 0; i < 4; i++) {
            const int idx = tid + i * 256;
            const int row = idx >> 3, g = idx & 7;
            cpa16(dst + row * LDA + g * 16, ls + row * 256 + g * 8);
        }
        cpa_commit();
    };
    auto load_b_regs = [&](int c) {
        const float* b0; int st;
        if (c < 4)      { st = 768; b0 = freq_k  + (size_t)k * 196608 + (size_t)c * 64 * 768 + v0; }
        else if (c < 8) { st = 256; b0 = freq_ki + (size_t)k * 65536  + (size_t)(c - 4) * 64 * 256 + v0; }
        else            { st = 768; b0 = freq_k  + (size_t)k * 196608 + (size_t)(c - 8) * 64 * 768 + 256 + v0; }
        hb[0] = __ldg((const float4*)(b0 + (size_t)br * st + bg * 8));
        hb[1] = __ldg((const float4*)(b0 + (size_t)br * st + bg * 8 + 4));
        if (c < 4) {
            const float* b1 = freq_k + (size_t)k * 196608 + (size_t)c * 64 * 768 + 512 + v0;
            hb[2] = __ldg((const float4*)(b1 + (size_t)br * 768 + bg * 8));
            hb[3] = __ldg((const float4*)(b1 + (size_t)br * 768 + bg * 8 + 4));
        }
    };
    auto store_b = [&](int c, uint32_t bp) {
        sts128(bp + br * LDB_H + bg * 16,
               packh(hb[0].x, hb[0].y), packh(hb[0].z, hb[0].w),
               packh(hb[1].x, hb[1].y), packh(hb[1].z, hb[1].w));
        if (c < 4) {
            sts128(bp + B_BYTES_H + br * LDB_H + bg * 16,
                   packh(hb[2].x, hb[2].y), packh(hb[2].z, hb[2].w),
                   packh(hb[3].x, hb[3].y), packh(hb[3].z, hb[3].w));
        }
    };

    // ---- prologue: LHS(0),LHS(1) in flight; B(0) converted; B(1) in regs ----
    load_lhs(0, L0);
    load_lhs(1, L1);
    load_b_regs(0);
    store_b(0, P0);
    load_b_regs(1);
    cpa_wait1();          // LHS(0) complete
    __syncthreads();

    uint32_t sL = L0;
    int lhs_next = 2;

#pragma unroll 1
    for (int c = 0; c < 12; c++) {
        const uint32_t sB0 = (c & 1) ? P1 : P0;
        const uint32_t sB1 = sB0 + B_BYTES_H;
        const uint32_t sBn = (c & 1) ? P0 : P1;

        // off-critical-path: convert B(c+1), launch loads for c+2
        if (c < 11) store_b(c + 1, sBn);
        if (c < 10) {
            const uint32_t dst = (lhs_next == 0) ? L0 : (lhs_next == 1) ? L1 : L2;
            load_lhs(c + 2, dst);
            load_b_regs(c + 2);
            lhs_next = (lhs_next == 2) ? 0 : lhs_next + 1;
        }

        // MMA over chunk c
        if (c < 4) {
#pragma unroll
            for (int s = 0; s < 4; s++) {
                uint32_t af[2][4], bf[4], bz[4];
                ldsm4(af[0], sL + a_base + s * 32);
                ldsm4(af[1], sL + a_base + 16 * LDA + s * 32);
                ldsm4t(bf, sB0 + b_base + s * 16 * LDB_H);
                ldsm4t(bz, sB1 + b_base + s * 16 * LDB_H);
#pragma unroll
                for (int mt = 0; mt < 2; mt++) {
                    mma_f16(acc_o[mt][0], af[mt], &bf[0]);
                    mma_f16(acc_o[mt][1], af[mt], &bf[2]);
                    mma_f16(acc_z[mt][0], af[mt], &bz[0]);
                    mma_f16(acc_z[mt][1], af[mt], &bz[2]);
                }
            }
        } else {
#pragma unroll
            for (int s = 0; s < 4; s++) {
                uint32_t af[2][4], bf[4];
                ldsm4(af[0], sL + a_base + s * 32);
                ldsm4(af[1], sL + a_base + 16 * LDA + s * 32);
                ldsm4t(bf, sB0 + b_base + s * 16 * LDB_H);
#pragma unroll
                for (int mt = 0; mt < 2; mt++) {
                    mma_f16(acc_o[mt][0], af[mt], &bf[0]);
                    mma_f16(acc_o[mt][1], af[mt], &bf[2]);
                }
            }
        }

        // pipeline barrier: LHS(c+1) complete; B(c+1) STS visible
        if (c < 11) {
            if (c == 10) cpa_wait0(); else cpa_wait1();
            __syncthreads();
        }

        sL = (sL == L0) ? L1 : (sL == L1) ? L2 : L0;
    }

    // ---- epilogue: zz = hsig(C_o + b_o) * tanh(C_z + b_z); z += zz ----------
    const float* bo = freqb + (size_t)k * 256;
    const float* bz = freqb + (size_t)(256 + k) * 256;
#pragma unroll
    for (int mt = 0; mt < 2; mt++)
#pragma unroll
        for (int j = 0; j < 2; j++)
#pragma unroll
            for (int r = 0; r < 4; r++) {
                const int b = wm * 32 + mt * 16 + (l >> 2) + (r >> 1) * 8;
                const int v = v0 + wn * 16 + j * 8 + (l & 3) * 2 + (r & 1);
                const float o = hsig(acc_o[mt][j][r] + __ldg(bo + v));
                const float zz = o * tanhf(acc_z[mt][j][r] + __ldg(bz + v));
                atomicAdd(&z_out[b * 256 + v], zz);
            }
}

// ============================================================================
// launch
// ============================================================================
extern "C" void kernel_launch(void* const* d_in, const int* in_sizes, int n_in,
                              void* d_out, int out_size)
{
    const float* x        = (const float*)d_in[0];
    const float* t        = (const float*)d_in[1];
    const float* z_prev   = (const float*)d_in[2];
    const float* Im_prev  = (const float*)d_in[3];
    const float* Re_prev  = (const float*)d_in[4];
    const float* omg_prev = (const float*)d_in[5];
    const float* kern     = (const float*)d_in[6];
    const float* recur    = (const float*)d_in[7];
    const float* freq_k   = (const float*)d_in[8];
    const float* freq_ki  = (const float*)d_in[9];
    const float* bias     = (const float*)d_in[10];
    const float* freqb    = (const float*)d_in[11];

    float* out     = (float*)d_out;
    float* z_out   = out;
    float* im_out  = out + 32768;
    float* re_out  = out + 32768 + 8388608;
    float* omg_out = out + 32768 + 2 * 8388608;

    static int smem_set = 0;
    if (!smem_set) {
        cudaFuncSetAttribute(k_freq_mma, cudaFuncAttributeMaxDynamicSharedMemorySize, SMEM_TOT);
        smem_set = 1;
    }

    cudaMemsetAsync(z_out, 0, 32768 * sizeof(float), 0);
    k_gates_gemm<<<dim3(20, 4), 256>>>(x, z_prev, kern, recur, bias);
    k_gates_ew<<<128, 256>>>(x, z_prev, omg_prev, t, omg_out);
    k_reim<<<dim3(4, 4, 128), 256>>>(Re_prev, Im_prev, im_out, re_out);
    k_freq_mma<<<dim3(8, 256), 256, SMEM_TOT>>>(freq_k, freq_ki, freqb, z_out);
}

// round 13
// speedup vs baseline: 1.1669x; 1.1669x over previous
#include <cuda_runtime.h>
#include <cuda_fp16.h>
#include <math.h>
#include <stdint.h>

#define Bq 128
#define Uq 256
#define NG 1280

// ---------------- scratch (static device globals) ----------------------------
__device__ float g_gsum[Bq * NG];
__device__ __half g_Ah[(size_t)Uq * Bq * Uq];  // [k][b][u], 16.8MB
__device__ __half g_xh[Bq * Uq];
__device__ __half g_zh[Bq * Uq];

__device__ __forceinline__ float hsig(float v) {
    return fminf(fmaxf(0.2f * v + 0.5f, 0.0f), 1.0f);
}

// ---------------- PTX helpers (sm_80-level only) ------------------------------
__device__ __forceinline__ uint32_t smem_u32(const void* p) {
    uint32_t a;
    asm("{ .reg .u64 t; cvta.to.shared.u64 t, %1; cvt.u32.u64 %0, t; }" : "=r"(a) : "l"(p));
    return a;
}
__device__ __forceinline__ uint32_t packh(float lo, float hi) {
    __half2 h = __floats2half2_rn(lo, hi);
    return *(uint32_t*)&h;
}
__device__ __forceinline__ void sts128(uint32_t a, uint32_t r0, uint32_t r1, uint32_t r2, uint32_t r3) {
    asm volatile("st.shared.v4.b32 [%0], {%1,%2,%3,%4};"
                 :: "r"(a), "r"(r0), "r"(r1), "r"(r2), "r"(r3) : "memory");
}
__device__ __forceinline__ void cpa16(uint32_t dst, const void* src) {
    asm volatile("cp.async.cg.shared.global [%0], [%1], 16;" :: "r"(dst), "l"(src) : "memory");
}
__device__ __forceinline__ void cpa_commit() {
    asm volatile("cp.async.commit_group;" ::: "memory");
}
__device__ __forceinline__ void cpa_wait0() {
    asm volatile("cp.async.wait_group 0;" ::: "memory");
}
__device__ __forceinline__ void cpa_wait1() {
    asm volatile("cp.async.wait_group 1;" ::: "memory");
}
__device__ __forceinline__ void ldsm4(uint32_t* r, uint32_t addr) {
    asm volatile("ldmatrix.sync.aligned.m8n8.x4.shared.b16 {%0,%1,%2,%3}, [%4];"
                 : "=r"(r[0]), "=r"(r[1]), "=r"(r[2]), "=r"(r[3]) : "r"(addr));
}
__device__ __forceinline__ void ldsm4t(uint32_t* r, uint32_t addr) {
    asm volatile("ldmatrix.sync.aligned.m8n8.x4.trans.shared.b16 {%0,%1,%2,%3}, [%4];"
                 : "=r"(r[0]), "=r"(r[1]), "=r"(r[2]), "=r"(r[3]) : "r"(addr));
}
__device__ __forceinline__ void mma_f16(float* c, const uint32_t* a, const uint32_t* b) {
    asm volatile(
        "mma.sync.aligned.m16n8k16.row.col.f32.f16.f16.f32 "
        "{%0,%1,%2,%3}, {%4,%5,%6,%7}, {%8,%9}, {%0,%1,%2,%3};"
        : "+f"(c[0]), "+f"(c[1]), "+f"(c[2]), "+f"(c[3])
        : "r"(a[0]), "r"(a[1]), "r"(a[2]), "r"(a[3]), "r"(b[0]), "r"(b[1]));
}

// ============================================================================
// Kernel 1: g_gsum = x @ kernel + z_prev @ recur_k + bias.  32x64 tiles.
// Epilogue extras: omg j-tiles write out_omg; low-u tiles convert x/z -> fp16
// and zero z_out (replaces k_gates_ew's prep duties + the memset).
// ============================================================================
__global__ __launch_bounds__(256) void k_gates_gemm(
    const float* __restrict__ x, const float* __restrict__ z_prev,
    const float* __restrict__ kern, const float* __restrict__ recur,
    const float* __restrict__ bias,
    float* __restrict__ out_omg, float* __restrict__ z_out)
{
    __shared__ float sX[32][33];
    __shared__ float sW[32][68];
    const int tid = threadIdx.x;
    const int j0 = blockIdx.x * 64, b0 = blockIdx.y * 32;
    const int rg = tid >> 4, cg = tid & 15;
    float acc[2][4];
#pragma unroll
    for (int i = 0; i < 2; i++)
#pragma unroll
        for (int j = 0; j < 4; j++) acc[i][j] = 0.f;

#pragma unroll
    for (int pass = 0; pass < 2; pass++) {
        const float* L = pass ? z_prev : x;
        const float* W = pass ? recur : kern;
        for (int d0 = 0; d0 < 256; d0 += 32) {
            {
                const int lb = tid >> 3, lu = (tid & 7) * 4;
                float4 v = *(const float4*)&L[(b0 + lb) * 256 + d0 + lu];
                sX[lu][lb] = v.x; sX[lu + 1][lb] = v.y;
                sX[lu + 2][lb] = v.z; sX[lu + 3][lb] = v.w;
            }
#pragma unroll
            for (int i2 = 0; i2 < 2; i2++) {
                const int wu = (tid >> 4) + i2 * 16, wc = (tid & 15) * 4;
                *(float4*)&sW[wu][wc] = *(const float4*)&W[(d0 + wu) * NG + j0 + wc];
            }
            __syncthreads();
#pragma unroll
            for (int kk = 0; kk < 32; kk++) {
                float a0 = sX[kk][rg * 2], a1 = sX[kk][rg * 2 + 1];
                float bb[4];
#pragma unroll
                for (int j = 0; j < 4; j++) bb[j] = sW[kk][cg * 4 + j];
#pragma unroll
                for (int j = 0; j < 4; j++) { acc[0][j] += a0 * bb[j]; acc[1][j] += a1 * bb[j]; }
            }
            __syncthreads();
        }
    }
#pragma unroll
    for (int i = 0; i < 2; i++) {
        const int b = b0 + rg * 2 + i;
#pragma unroll
        for (int j = 0; j < 4; j++) {
            const int jj = j0 + cg * 4 + j;
            const float val = acc[i][j] + bias[jj];
            g_gsum[b * NG + jj] = val;
            if (jj >= 1024) out_omg[b * 256 + jj - 1024] = val;
        }
    }
    // extra duties for the 4 low-u j-tiles: x/z fp16 conversion + z_out zeroing
    if (blockIdx.x < 4) {
        const int u0 = (int)blockIdx.x * 64;
#pragma unroll
        for (int e = 0; e < 8; e++) {
            const int idx = tid + e * 256;             // 0..2047 over 32b x 64u
            const int bb = b0 + (idx >> 6);
            const int uu = u0 + (idx & 63);
            const int gi = bb * 256 + uu;
            g_xh[gi] = __float2half_rn(x[gi]);
            g_zh[gi] = __float2half_rn(z_prev[gi]);
            z_out[gi] = 0.f;
        }
    }
}

// ============================================================================
// Kernel 2: Re/Im update + A = sqrt(Re^2+Im^2) -> g_Ah [k][b][u] (fp16).
// Gate transforms (hsig/tanh/cos/sin) recomputed inline from g_gsum
// (bitwise-identical formulas to the old k_gates_ew).
// ============================================================================
__global__ __launch_bounds__(256) void k_reim(
    const float* __restrict__ Re_prev, const float* __restrict__ Im_prev,
    const float* __restrict__ omg_prev, const float* __restrict__ t,
    float* __restrict__ Im_out, float* __restrict__ Re_out)
{
    __shared__ float sA[64][65];
    const int b = blockIdx.z, i0 = blockIdx.y * 64, j0 = blockIdx.x * 64;
    const int t16 = threadIdx.x & 15, tr = threadIdx.x >> 4;
    const int j4 = t16 * 4;

    const float* gs = g_gsum + b * NG;
    const float tb = t[b];

    // j-dependent gate values (f-gate -> fre; omg_prev*t -> cos/sin)
    const float4 gf4 = *(const float4*)&gs[256 + j0 + j4];
    const float4 op4 = *(const float4*)&omg_prev[b * Uq + j0 + j4];
    const float gfv[4] = {gf4.x, gf4.y, gf4.z, gf4.w};
    const float opv[4] = {op4.x, op4.y, op4.z, op4.w};
    float frev[4], cosv[4], sinv[4];
#pragma unroll
    for (int q = 0; q < 4; q++) {
        frev[q] = hsig(gfv[q]);
        const float th = opv[q] * tb;
        cosv[q] = cosf(th);
        sinv[q] = sinf(th);
    }

#pragma unroll
    for (int r = 0; r < 4; r++) {
        const int i = tr + r * 16;
        // i-dependent gates: ste = hsig(s), c = hsig(i)*tanh(g)
        const float ste_i = hsig(gs[512 + i0 + i]);
        const float ci    = hsig(gs[i0 + i]) * tanhf(gs[768 + i0 + i]);
        const size_t idx = ((size_t)b * Uq + (i0 + i)) * Uq + j0 + j4;
        const float4 rp = *(const float4*)&Re_prev[idx];
        const float4 ip = *(const float4*)&Im_prev[idx];
        const float rpv[4] = {rp.x, rp.y, rp.z, rp.w};
        const float ipv[4] = {ip.x, ip.y, ip.z, ip.w};
        float rev[4], imv[4];
#pragma unroll
        for (int q = 0; q < 4; q++) {
            const float f = ste_i * frev[q];
            rev[q] = f * rpv[q] + ci * cosv[q];
            imv[q] = f * ipv[q] + ci * sinv[q];
            sA[i][j4 + q] = sqrtf(rev[q] * rev[q] + imv[q] * imv[q]);
        }
        *(float4*)&Re_out[idx] = make_float4(rev[0], rev[1], rev[2], rev[3]);
        *(float4*)&Im_out[idx] = make_float4(imv[0], imv[1], imv[2], imv[3]);
    }
    __syncthreads();
#pragma unroll
    for (int r = 0; r < 4; r++) {
        const int j = tr + r * 16;
        const int i4 = t16 * 4;
        __half2 h0 = __floats2half2_rn(sA[i4][j],     sA[i4 + 1][j]);
        __half2 h1 = __floats2half2_rn(sA[i4 + 2][j], sA[i4 + 3][j]);
        uint2 v = make_uint2(*(uint32_t*)&h0, *(uint32_t*)&h1);
        *(uint2*)&g_Ah[((size_t)(j0 + j) * 128 + b) * 256 + i0 + i4] = v;
    }
}

// ============================================================================
// Kernel 3: per-k fused GEMMs via mma.sync fp16 -- R11 kernel, unchanged.
// Grid (4 vq, 256 k). 256 threads, warps 4(M)x2(N), warp tile 32x32.
// Chunks of K=64:  c 0-3:  A @ [U_o | W_z]  -> acc_o, acc_z
//                  c 4-7:  x @ W_o          -> acc_o
//                  c 8-11: z_prev @ V_o     -> acc_o
// Distance-2 pipeline: 3 LHS cp.async slots, 2 B-pair slots (LDG->cvt->STS).
// ============================================================================
#define LDA 144                 // 64 fp16 (128B) + 16B pad
#define LDB 144
#define L_BYTES (128*LDA)       // 18432 per LHS slot
#define B_BYTES (64*LDB)        // 9216 per B tile
#define BP_BYTES (2*B_BYTES)    // 18432 per B pair slot
#define SMEM_TOT (3*L_BYTES + 2*BP_BYTES)   // 92160

__global__ __launch_bounds__(256, 2) void k_freq_mma(
    const float* __restrict__ freq_k, const float* __restrict__ freq_ki,
    const float* __restrict__ freqb, float* __restrict__ z_out)
{
    extern __shared__ char smem[];
    const uint32_t sbase = smem_u32(smem);
    const int tid = threadIdx.x, l = tid & 31, w = tid >> 5;
    const int wm = w & 3, wn = w >> 2;
    const int k = blockIdx.y, v0 = blockIdx.x * 64;

    const uint32_t L0 = sbase, L1 = sbase + L_BYTES, L2 = sbase + 2 * L_BYTES;
    const uint32_t P0 = sbase + 3 * L_BYTES, P1 = P0 + BP_BYTES;

    float acc_o[2][4][4], acc_z[2][4][4];
#pragma unroll
    for (int i = 0; i < 32; i++) { ((float*)acc_o)[i] = 0.f; ((float*)acc_z)[i] = 0.f; }

    const uint32_t a_base = (uint32_t)((wm * 32 + (l & 15)) * LDA + (l >> 4) * 16);
    const uint32_t b_base = (uint32_t)((l & 15) * LDB + wn * 64 + (l >> 4) * 16);

    float4 hb[8];

    auto load_lhs = [&](int c, uint32_t dst) {
        const __half* ls;
        if (c < 4)      ls = g_Ah + (size_t)k * 32768 + c * 64;
        else if (c < 8) ls = g_xh + (c - 4) * 64;
        else            ls = g_zh + (c - 8) * 64;
#pragma unroll
        for (int i = 0; i < 4; i++) {
            const int idx = tid + i * 256;
            const int row = idx >> 3, g = idx & 7;
            cpa16(dst + row * LDA + g * 16, ls + row * 256 + g * 8);
        }
        cpa_commit();
    };
    auto load_b_regs = [&](int c) {
        const float* b0; int st;
        if (c < 4)      { st = 768; b0 = freq_k  + (size_t)k * 196608 + (size_t)c * 64 * 768 + v0; }
        else if (c < 8) { st = 256; b0 = freq_ki + (size_t)k * 65536  + (size_t)(c - 4) * 64 * 256 + v0; }
        else            { st = 768; b0 = freq_k  + (size_t)k * 196608 + (size_t)(c - 8) * 64 * 768 + 256 + v0; }
#pragma unroll
        for (int i = 0; i < 2; i++) {
            const int idx = tid + i * 256;
            const int r = idx >> 3, g = idx & 7;
            hb[2 * i]     = __ldg((const float4*)(b0 + (size_t)r * st + g * 8));
            hb[2 * i + 1] = __ldg((const float4*)(b0 + (size_t)r * st + g * 8 + 4));
        }
        if (c < 4) {
            const float* b1 = freq_k + (size_t)k * 196608 + (size_t)c * 64 * 768 + 512 + v0;
#pragma unroll
            for (int i = 0; i < 2; i++) {
                const int idx = tid + i * 256;
                const int r = idx >> 3, g = idx & 7;
                hb[4 + 2 * i] = __ldg((const float4*)(b1 + (size_t)r * 768 + g * 8));
                hb[5 + 2 * i] = __ldg((const float4*)(b1 + (size_t)r * 768 + g * 8 + 4));
            }
        }
    };
    auto store_b = [&](int c, uint32_t bp) {
#pragma unroll
        for (int i = 0; i < 2; i++) {
            const int idx = tid + i * 256;
            const int r = idx >> 3, g = idx & 7;
            sts128(bp + r * LDB + g * 16,
                   packh(hb[2 * i].x, hb[2 * i].y), packh(hb[2 * i].z, hb[2 * i].w),
                   packh(hb[2 * i + 1].x, hb[2 * i + 1].y), packh(hb[2 * i + 1].z, hb[2 * i + 1].w));
        }
        if (c < 4) {
#pragma unroll
            for (int i = 0; i < 2; i++) {
                const int idx = tid + i * 256;
                const int r = idx >> 3, g = idx & 7;
                sts128(bp + B_BYTES + r * LDB + g * 16,
                       packh(hb[4 + 2 * i].x, hb[4 + 2 * i].y), packh(hb[4 + 2 * i].z, hb[4 + 2 * i].w),
                       packh(hb[5 + 2 * i].x, hb[5 + 2 * i].y), packh(hb[5 + 2 * i].z, hb[5 + 2 * i].w));
            }
        }
    };

    // ---- prologue: LHS(0),LHS(1) in flight; B(0) converted; B(1) in regs ----
    load_lhs(0, L0);
    load_lhs(1, L1);
    load_b_regs(0);
    store_b(0, P0);
    load_b_regs(1);
    cpa_wait1();          // LHS(0) complete
    __syncthreads();

    uint32_t sL = L0;
    int lhs_next = 2;

#pragma unroll 1
    for (int c = 0; c < 12; c++) {
        const uint32_t sB0 = (c & 1) ? P1 : P0;
        const uint32_t sB1 = sB0 + B_BYTES;
        const uint32_t sBn = (c & 1) ? P0 : P1;

        // off-critical-path work: convert B(c+1), launch loads for c+2
        if (c < 11) store_b(c + 1, sBn);
        if (c < 10) {
            const uint32_t dst = (lhs_next == 0) ? L0 : (lhs_next == 1) ? L1 : L2;
            load_lhs(c + 2, dst);
            load_b_regs(c + 2);
            lhs_next = (lhs_next == 2) ? 0 : lhs_next + 1;
        }

        // MMA over chunk c
        if (c < 4) {
#pragma unroll
            for (int s = 0; s < 4; s++) {
                uint32_t af[2][4], bf[2][4], bz[2][4];
                ldsm4(af[0], sL + a_base + s * 32);
                ldsm4(af[1], sL + a_base + 16 * LDA + s * 32);
#pragma unroll
                for (int nt = 0; nt < 2; nt++) {
                    ldsm4t(bf[nt], sB0 + b_base + s * 16 * LDB + nt * 32);
                    ldsm4t(bz[nt], sB1 + b_base + s * 16 * LDB + nt * 32);
                }
#pragma unroll
                for (int mt = 0; mt < 2; mt++)
#pragma unroll
                    for (int nt = 0; nt < 2; nt++) {
                        mma_f16(acc_o[mt][2 * nt],     af[mt], &bf[nt][0]);
                        mma_f16(acc_o[mt][2 * nt + 1], af[mt], &bf[nt][2]);
                        mma_f16(acc_z[mt][2 * nt],     af[mt], &bz[nt][0]);
                        mma_f16(acc_z[mt][2 * nt + 1], af[mt], &bz[nt][2]);
                    }
            }
        } else {
#pragma unroll
            for (int s = 0; s < 4; s++) {
                uint32_t af[2][4], bf[2][4];
                ldsm4(af[0], sL + a_base + s * 32);
                ldsm4(af[1], sL + a_base + 16 * LDA + s * 32);
#pragma unroll
                for (int nt = 0; nt < 2; nt++)
                    ldsm4t(bf[nt], sB0 + b_base + s * 16 * LDB + nt * 32);
#pragma unroll
                for (int mt = 0; mt < 2; mt++)
#pragma unroll
                    for (int nt = 0; nt < 2; nt++) {
                        mma_f16(acc_o[mt][2 * nt],     af[mt], &bf[nt][0]);
                        mma_f16(acc_o[mt][2 * nt + 1], af[mt], &bf[nt][2]);
                    }
            }
        }

        // pipeline barrier: LHS(c+1) complete; B(c+1) STS visible
        if (c < 11) {
            if (c == 10) cpa_wait0(); else cpa_wait1();
            __syncthreads();
        }

        sL = (sL == L0) ? L1 : (sL == L1) ? L2 : L0;
    }

    // ---- epilogue: zz = hsig(C_o + b_o) * tanh(C_z + b_z); z += zz ----------
    const float* bo = freqb + (size_t)k * 256;
    const float* bz = freqb + (size_t)(256 + k) * 256;
#pragma unroll
    for (int mt = 0; mt < 2; mt++)
#pragma unroll
        for (int j = 0; j < 4; j++)
#pragma unroll
            for (int r = 0; r < 4; r++) {
                const int b = wm * 32 + mt * 16 + (l >> 2) + (r >> 1) * 8;
                const int v = v0 + wn * 32 + j * 8 + (l & 3) * 2 + (r & 1);
                const float o = hsig(acc_o[mt][j][r] + __ldg(bo + v));
                const float zz = o * tanhf(acc_z[mt][j][r] + __ldg(bz + v));
                atomicAdd(&z_out[b * 256 + v], zz);
            }
}

// ============================================================================
// launch
// ============================================================================
extern "C" void kernel_launch(void* const* d_in, const int* in_sizes, int n_in,
                              void* d_out, int out_size)
{
    const float* x        = (const float*)d_in[0];
    const float* t        = (const float*)d_in[1];
    const float* z_prev   = (const float*)d_in[2];
    const float* Im_prev  = (const float*)d_in[3];
    const float* Re_prev  = (const float*)d_in[4];
    const float* omg_prev = (const float*)d_in[5];
    const float* kern     = (const float*)d_in[6];
    const float* recur    = (const float*)d_in[7];
    const float* freq_k   = (const float*)d_in[8];
    const float* freq_ki  = (const float*)d_in[9];
    const float* bias     = (const float*)d_in[10];
    const float* freqb    = (const float*)d_in[11];

    float* out     = (float*)d_out;
    float* z_out   = out;
    float* im_out  = out + 32768;
    float* re_out  = out + 32768 + 8388608;
    float* omg_out = out + 32768 + 2 * 8388608;

    static int smem_set = 0;
    if (!smem_set) {
        cudaFuncSetAttribute(k_freq_mma, cudaFuncAttributeMaxDynamicSharedMemorySize, SMEM_TOT);
        smem_set = 1;
    }

    k_gates_gemm<<<dim3(20, 4), 256>>>(x, z_prev, kern, recur, bias, omg_out, z_out);
    k_reim<<<dim3(4, 4, 128), 256>>>(Re_prev, Im_prev, omg_prev, t, im_out, re_out);
    k_freq_mma<<<dim3(4, 256), 256, SMEM_TOT>>>(freq_k, freq_ki, freqb, z_out);
}

// round 14
// speedup vs baseline: 1.2947x; 1.1096x over previous
#include <cuda_runtime.h>
#include <cuda_fp16.h>
#include <math.h>
#include <stdint.h>

#define Bq 128
#define Uq 256
#define NG 1280

// ---------------- scratch (static device globals) ----------------------------
__device__ float g_gx[Bq * NG];                // x @ kernel partial
__device__ float g_gz[Bq * NG];                // z_prev @ recur_k partial
__device__ __half g_Ah[(size_t)Uq * Bq * Uq];  // [k][b][u], 16.8MB
__device__ __half g_xh[Bq * Uq];
__device__ __half g_zh[Bq * Uq];

__device__ __forceinline__ float hsig(float v) {
    return fminf(fmaxf(0.2f * v + 0.5f, 0.0f), 1.0f);
}

// ---------------- PTX helpers (sm_80-level only) ------------------------------
__device__ __forceinline__ uint32_t smem_u32(const void* p) {
    uint32_t a;
    asm("{ .reg .u64 t; cvta.to.shared.u64 t, %1; cvt.u32.u64 %0, t; }" : "=r"(a) : "l"(p));
    return a;
}
__device__ __forceinline__ uint32_t packh(float lo, float hi) {
    __half2 h = __floats2half2_rn(lo, hi);
    return *(uint32_t*)&h;
}
__device__ __forceinline__ void sts128(uint32_t a, uint32_t r0, uint32_t r1, uint32_t r2, uint32_t r3) {
    asm volatile("st.shared.v4.b32 [%0], {%1,%2,%3,%4};"
                 :: "r"(a), "r"(r0), "r"(r1), "r"(r2), "r"(r3) : "memory");
}
__device__ __forceinline__ void cpa16(uint32_t dst, const void* src) {
    asm volatile("cp.async.cg.shared.global [%0], [%1], 16;" :: "r"(dst), "l"(src) : "memory");
}
__device__ __forceinline__ void cpa_commit() {
    asm volatile("cp.async.commit_group;" ::: "memory");
}
__device__ __forceinline__ void cpa_wait0() {
    asm volatile("cp.async.wait_group 0;" ::: "memory");
}
__device__ __forceinline__ void cpa_wait1() {
    asm volatile("cp.async.wait_group 1;" ::: "memory");
}
__device__ __forceinline__ void ldsm4(uint32_t* r, uint32_t addr) {
    asm volatile("ldmatrix.sync.aligned.m8n8.x4.shared.b16 {%0,%1,%2,%3}, [%4];"
                 : "=r"(r[0]), "=r"(r[1]), "=r"(r[2]), "=r"(r[3]) : "r"(addr));
}
__device__ __forceinline__ void ldsm4t(uint32_t* r, uint32_t addr) {
    asm volatile("ldmatrix.sync.aligned.m8n8.x4.trans.shared.b16 {%0,%1,%2,%3}, [%4];"
                 : "=r"(r[0]), "=r"(r[1]), "=r"(r[2]), "=r"(r[3]) : "r"(addr));
}
__device__ __forceinline__ void mma_f16(float* c, const uint32_t* a, const uint32_t* b) {
    asm volatile(
        "mma.sync.aligned.m16n8k16.row.col.f32.f16.f16.f32 "
        "{%0,%1,%2,%3}, {%4,%5,%6,%7}, {%8,%9}, {%0,%1,%2,%3};"
        : "+f"(c[0]), "+f"(c[1]), "+f"(c[2]), "+f"(c[3])
        : "r"(a[0]), "r"(a[1]), "r"(a[2]), "r"(a[3]), "r"(b[0]), "r"(b[1]));
}

// ============================================================================
// Kernel 1: gate GEMM partials, K-split across blocks.
// Grid (20 j, 4 b, 2 pass). pass0: g_gx = x @ kernel; pass1: g_gz = z @ recur.
// 32(b) x 64(j) tile, 8 K-chunks of 32, cp.async double buffer for W,
// register prefetch for the LHS transpose tile.
// pass0 & blockIdx.x<4 blocks also: x/z -> fp16 and z_out zeroing.
// ============================================================================
__global__ __launch_bounds__(256) void k_gates_gemm(
    const float* __restrict__ x, const float* __restrict__ z_prev,
    const float* __restrict__ kern, const float* __restrict__ recur,
    float* __restrict__ z_out)
{
    __shared__ float sX[2][32][33];
    __shared__ float sW[2][32][64];
    const int tid = threadIdx.x;
    const int j0 = blockIdx.x * 64, b0 = blockIdx.y * 32;
    const int pass = blockIdx.z;
    const float* L = pass ? z_prev : x;
    const float* W = pass ? recur : kern;
    float* G = pass ? g_gz : g_gx;
    const int rg = tid >> 4, cg = tid & 15;
    const int lb = tid >> 3, lu = (tid & 7) * 4;   // LHS loader coords
    const int wr = tid >> 4, wc4 = (tid & 15) * 4; // W loader: rows wr, wr+16

    const uint32_t sW0 = smem_u32(&sW[0][0][0]);
    const uint32_t sW1 = smem_u32(&sW[1][0][0]);

    float acc[2][4];
#pragma unroll
    for (int i = 0; i < 2; i++)
#pragma unroll
        for (int j = 0; j < 4; j++) acc[i][j] = 0.f;

    auto cpa_w = [&](int d0, uint32_t sw) {
        cpa16(sw + (wr * 64 + wc4) * 4,        W + (size_t)(d0 + wr) * NG + j0 + wc4);
        cpa16(sw + ((wr + 16) * 64 + wc4) * 4, W + (size_t)(d0 + wr + 16) * NG + j0 + wc4);
        cpa_commit();
    };

    // ---- prologue: chunk 0 -------------------------------------------------
    float4 xv = *(const float4*)&L[(b0 + lb) * 256 + lu];
    cpa_w(0, sW0);
    sX[0][lu + 0][lb] = xv.x; sX[0][lu + 1][lb] = xv.y;
    sX[0][lu + 2][lb] = xv.z; sX[0][lu + 3][lb] = xv.w;
    cpa_wait0();
    __syncthreads();

#pragma unroll 1
    for (int c = 0; c < 8; c++) {
        const int buf = c & 1;
        if (c < 7) {
            const int d0 = (c + 1) * 32;
            xv = *(const float4*)&L[(b0 + lb) * 256 + d0 + lu];
            cpa_w(d0, buf ? sW0 : sW1);
        }
#pragma unroll
        for (int kk = 0; kk < 32; kk++) {
            const float a0 = sX[buf][kk][rg * 2];
            const float a1 = sX[buf][kk][rg * 2 + 1];
            float bb[4];
#pragma unroll
            for (int j = 0; j < 4; j++) bb[j] = sW[buf][kk][cg * 4 + j];
#pragma unroll
            for (int j = 0; j < 4; j++) { acc[0][j] += a0 * bb[j]; acc[1][j] += a1 * bb[j]; }
        }
        if (c < 7) {
            const int nb = buf ^ 1;
            sX[nb][lu + 0][lb] = xv.x; sX[nb][lu + 1][lb] = xv.y;
            sX[nb][lu + 2][lb] = xv.z; sX[nb][lu + 3][lb] = xv.w;
            cpa_wait0();
            __syncthreads();
        }
    }

#pragma unroll
    for (int i = 0; i < 2; i++) {
        const int b = b0 + rg * 2 + i;
#pragma unroll
        for (int j = 0; j < 4; j++)
            G[b * NG + j0 + cg * 4 + j] = acc[i][j];
    }

    // extra duties (pass 0, low-u j-tiles): x/z fp16 conversion + z_out zeroing
    if (pass == 0 && blockIdx.x < 4) {
        const int u0 = (int)blockIdx.x * 64;
#pragma unroll
        for (int e = 0; e < 8; e++) {
            const int idx = tid + e * 256;
            const int bb = b0 + (idx >> 6);
            const int uu = u0 + (idx & 63);
            const int gi = bb * 256 + uu;
            g_xh[gi] = __float2half_rn(x[gi]);
            g_zh[gi] = __float2half_rn(z_prev[gi]);
            z_out[gi] = 0.f;
        }
    }
}

// ============================================================================
// Kernel 2: Re/Im update + A = sqrt(Re^2+Im^2) -> g_Ah [k][b][u] (fp16).
// Gate transforms computed inline from g_gx + g_gz + bias.
// Blocks with i0==0 also write out_omg for their j-range.
// ============================================================================
__global__ __launch_bounds__(256) void k_reim(
    const float* __restrict__ Re_prev, const float* __restrict__ Im_prev,
    const float* __restrict__ omg_prev, const float* __restrict__ t,
    const float* __restrict__ bias,
    float* __restrict__ Im_out, float* __restrict__ Re_out,
    float* __restrict__ out_omg)
{
    __shared__ float sA[64][65];
    const int b = blockIdx.z, i0 = blockIdx.y * 64, j0 = blockIdx.x * 64;
    const int t16 = threadIdx.x & 15, tr = threadIdx.x >> 4;
    const int j4 = t16 * 4;

    const float* gx = g_gx + b * NG;
    const float* gz = g_gz + b * NG;
    const float tb = t[b];

    if (blockIdx.y == 0 && threadIdx.x < 64) {
        const int j = j0 + threadIdx.x;
        out_omg[b * 256 + j] = gx[1024 + j] + gz[1024 + j] + bias[1024 + j];
    }

    // j-dependent gates: fre = hsig(f-pre); theta = omg_prev * t
    const float4 fx4 = *(const float4*)&gx[256 + j0 + j4];
    const float4 fz4 = *(const float4*)&gz[256 + j0 + j4];
    const float4 fb4 = *(const float4*)&bias[256 + j0 + j4];
    const float4 op4 = *(const float4*)&omg_prev[b * Uq + j0 + j4];
    const float gfv[4] = {fx4.x + fz4.x + fb4.x, fx4.y + fz4.y + fb4.y,
                          fx4.z + fz4.z + fb4.z, fx4.w + fz4.w + fb4.w};
    const float opv[4] = {op4.x, op4.y, op4.z, op4.w};
    float frev[4], cosv[4], sinv[4];
#pragma unroll
    for (int q = 0; q < 4; q++) {
        frev[q] = hsig(gfv[q]);
        const float th = opv[q] * tb;
        cosv[q] = cosf(th);
        sinv[q] = sinf(th);
    }

#pragma unroll
    for (int r = 0; r < 4; r++) {
        const int i = tr + r * 16;
        const int ii = i0 + i;
        const float ste_i = hsig(gx[512 + ii] + gz[512 + ii] + bias[512 + ii]);
        const float ci    = hsig(gx[ii] + gz[ii] + bias[ii])
                          * tanhf(gx[768 + ii] + gz[768 + ii] + bias[768 + ii]);
        const size_t idx = ((size_t)b * Uq + ii) * Uq + j0 + j4;
        const float4 rp = *(const float4*)&Re_prev[idx];
        const float4 ip = *(const float4*)&Im_prev[idx];
        const float rpv[4] = {rp.x, rp.y, rp.z, rp.w};
        const float ipv[4] = {ip.x, ip.y, ip.z, ip.w};
        float rev[4], imv[4];
#pragma unroll
        for (int q = 0; q < 4; q++) {
            const float f = ste_i * frev[q];
            rev[q] = f * rpv[q] + ci * cosv[q];
            imv[q] = f * ipv[q] + ci * sinv[q];
            sA[i][j4 + q] = sqrtf(rev[q] * rev[q] + imv[q] * imv[q]);
        }
        *(float4*)&Re_out[idx] = make_float4(rev[0], rev[1], rev[2], rev[3]);
        *(float4*)&Im_out[idx] = make_float4(imv[0], imv[1], imv[2], imv[3]);
    }
    __syncthreads();
#pragma unroll
    for (int r = 0; r < 4; r++) {
        const int j = tr + r * 16;
        const int i4 = t16 * 4;
        __half2 h0 = __floats2half2_rn(sA[i4][j],     sA[i4 + 1][j]);
        __half2 h1 = __floats2half2_rn(sA[i4 + 2][j], sA[i4 + 3][j]);
        uint2 v = make_uint2(*(uint32_t*)&h0, *(uint32_t*)&h1);
        *(uint2*)&g_Ah[((size_t)(j0 + j) * 128 + b) * 256 + i0 + i4] = v;
    }
}

// ============================================================================
// Kernel 3: per-k fused GEMMs via mma.sync fp16 -- R11 kernel, unchanged.
// Grid (4 vq, 256 k). 256 threads, warps 4(M)x2(N), warp tile 32x32.
// Chunks of K=64:  c 0-3:  A @ [U_o | W_z]  -> acc_o, acc_z
//                  c 4-7:  x @ W_o          -> acc_o
//                  c 8-11: z_prev @ V_o     -> acc_o
// Distance-2 pipeline: 3 LHS cp.async slots, 2 B-pair slots (LDG->cvt->STS).
// ============================================================================
#define LDA 144                 // 64 fp16 (128B) + 16B pad
#define LDB 144
#define L_BYTES (128*LDA)       // 18432 per LHS slot
#define B_BYTES (64*LDB)        // 9216 per B tile
#define BP_BYTES (2*B_BYTES)    // 18432 per B pair slot
#define SMEM_TOT (3*L_BYTES + 2*BP_BYTES)   // 92160

__global__ __launch_bounds__(256, 2) void k_freq_mma(
    const float* __restrict__ freq_k, const float* __restrict__ freq_ki,
    const float* __restrict__ freqb, float* __restrict__ z_out)
{
    extern __shared__ char smem[];
    const uint32_t sbase = smem_u32(smem);
    const int tid = threadIdx.x, l = tid & 31, w = tid >> 5;
    const int wm = w & 3, wn = w >> 2;
    const int k = blockIdx.y, v0 = blockIdx.x * 64;

    const uint32_t L0 = sbase, L1 = sbase + L_BYTES, L2 = sbase + 2 * L_BYTES;
    const uint32_t P0 = sbase + 3 * L_BYTES, P1 = P0 + BP_BYTES;

    float acc_o[2][4][4], acc_z[2][4][4];
#pragma unroll
    for (int i = 0; i < 32; i++) { ((float*)acc_o)[i] = 0.f; ((float*)acc_z)[i] = 0.f; }

    const uint32_t a_base = (uint32_t)((wm * 32 + (l & 15)) * LDA + (l >> 4) * 16);
    const uint32_t b_base = (uint32_t)((l & 15) * LDB + wn * 64 + (l >> 4) * 16);

    float4 hb[8];

    auto load_lhs = [&](int c, uint32_t dst) {
        const __half* ls;
        if (c < 4)      ls = g_Ah + (size_t)k * 32768 + c * 64;
        else if (c < 8) ls = g_xh + (c - 4) * 64;
        else            ls = g_zh + (c - 8) * 64;
#pragma unroll
        for (int i = 0; i < 4; i++) {
            const int idx = tid + i * 256;
            const int row = idx >> 3, g = idx & 7;
            cpa16(dst + row * LDA + g * 16, ls + row * 256 + g * 8);
        }
        cpa_commit();
    };
    auto load_b_regs = [&](int c) {
        const float* b0; int st;
        if (c < 4)      { st = 768; b0 = freq_k  + (size_t)k * 196608 + (size_t)c * 64 * 768 + v0; }
        else if (c < 8) { st = 256; b0 = freq_ki + (size_t)k * 65536  + (size_t)(c - 4) * 64 * 256 + v0; }
        else            { st = 768; b0 = freq_k  + (size_t)k * 196608 + (size_t)(c - 8) * 64 * 768 + 256 + v0; }
#pragma unroll
        for (int i = 0; i < 2; i++) {
            const int idx = tid + i * 256;
            const int r = idx >> 3, g = idx & 7;
            hb[2 * i]     = __ldg((const float4*)(b0 + (size_t)r * st + g * 8));
            hb[2 * i + 1] = __ldg((const float4*)(b0 + (size_t)r * st + g * 8 + 4));
        }
        if (c < 4) {
            const float* b1 = freq_k + (size_t)k * 196608 + (size_t)c * 64 * 768 + 512 + v0;
#pragma unroll
            for (int i = 0; i < 2; i++) {
                const int idx = tid + i * 256;
                const int r = idx >> 3, g = idx & 7;
                hb[4 + 2 * i] = __ldg((const float4*)(b1 + (size_t)r * 768 + g * 8));
                hb[5 + 2 * i] = __ldg((const float4*)(b1 + (size_t)r * 768 + g * 8 + 4));
            }
        }
    };
    auto store_b = [&](int c, uint32_t bp) {
#pragma unroll
        for (int i = 0; i < 2; i++) {
            const int idx = tid + i * 256;
            const int r = idx >> 3, g = idx & 7;
            sts128(bp + r * LDB + g * 16,
                   packh(hb[2 * i].x, hb[2 * i].y), packh(hb[2 * i].z, hb[2 * i].w),
                   packh(hb[2 * i + 1].x, hb[2 * i + 1].y), packh(hb[2 * i + 1].z, hb[2 * i + 1].w));
        }
        if (c < 4) {
#pragma unroll
            for (int i = 0; i < 2; i++) {
                const int idx = tid + i * 256;
                const int r = idx >> 3, g = idx & 7;
                sts128(bp + B_BYTES + r * LDB + g * 16,
                       packh(hb[4 + 2 * i].x, hb[4 + 2 * i].y), packh(hb[4 + 2 * i].z, hb[4 + 2 * i].w),
                       packh(hb[5 + 2 * i].x, hb[5 + 2 * i].y), packh(hb[5 + 2 * i].z, hb[5 + 2 * i].w));
            }
        }
    };

    // ---- prologue: LHS(0),LHS(1) in flight; B(0) converted; B(1) in regs ----
    load_lhs(0, L0);
    load_lhs(1, L1);
    load_b_regs(0);
    store_b(0, P0);
    load_b_regs(1);
    cpa_wait1();          // LHS(0) complete
    __syncthreads();

    uint32_t sL = L0;
    int lhs_next = 2;

#pragma unroll 1
    for (int c = 0; c < 12; c++) {
        const uint32_t sB0 = (c & 1) ? P1 : P0;
        const uint32_t sB1 = sB0 + B_BYTES;
        const uint32_t sBn = (c & 1) ? P0 : P1;

        // off-critical-path work: convert B(c+1), launch loads for c+2
        if (c < 11) store_b(c + 1, sBn);
        if (c < 10) {
            const uint32_t dst = (lhs_next == 0) ? L0 : (lhs_next == 1) ? L1 : L2;
            load_lhs(c + 2, dst);
            load_b_regs(c + 2);
            lhs_next = (lhs_next == 2) ? 0 : lhs_next + 1;
        }

        // MMA over chunk c
        if (c < 4) {
#pragma unroll
            for (int s = 0; s < 4; s++) {
                uint32_t af[2][4], bf[2][4], bz[2][4];
                ldsm4(af[0], sL + a_base + s * 32);
                ldsm4(af[1], sL + a_base + 16 * LDA + s * 32);
#pragma unroll
                for (int nt = 0; nt < 2; nt++) {
                    ldsm4t(bf[nt], sB0 + b_base + s * 16 * LDB + nt * 32);
                    ldsm4t(bz[nt], sB1 + b_base + s * 16 * LDB + nt * 32);
                }
#pragma unroll
                for (int mt = 0; mt < 2; mt++)
#pragma unroll
                    for (int nt = 0; nt < 2; nt++) {
                        mma_f16(acc_o[mt][2 * nt],     af[mt], &bf[nt][0]);
                        mma_f16(acc_o[mt][2 * nt + 1], af[mt], &bf[nt][2]);
                        mma_f16(acc_z[mt][2 * nt],     af[mt], &bz[nt][0]);
                        mma_f16(acc_z[mt][2 * nt + 1], af[mt], &bz[nt][2]);
                    }
            }
        } else {
#pragma unroll
            for (int s = 0; s < 4; s++) {
                uint32_t af[2][4], bf[2][4];
                ldsm4(af[0], sL + a_base + s * 32);
                ldsm4(af[1], sL + a_base + 16 * LDA + s * 32);
#pragma unroll
                for (int nt = 0; nt < 2; nt++)
                    ldsm4t(bf[nt], sB0 + b_base + s * 16 * LDB + nt * 32);
#pragma unroll
                for (int mt = 0; mt < 2; mt++)
#pragma unroll
                    for (int nt = 0; nt < 2; nt++) {
                        mma_f16(acc_o[mt][2 * nt],     af[mt], &bf[nt][0]);
                        mma_f16(acc_o[mt][2 * nt + 1], af[mt], &bf[nt][2]);
                    }
            }
        }

        // pipeline barrier: LHS(c+1) complete; B(c+1) STS visible
        if (c < 11) {
            if (c == 10) cpa_wait0(); else cpa_wait1();
            __syncthreads();
        }

        sL = (sL == L0) ? L1 : (sL == L1) ? L2 : L0;
    }

    // ---- epilogue: zz = hsig(C_o + b_o) * tanh(C_z + b_z); z += zz ----------
    const float* bo = freqb + (size_t)k * 256;
    const float* bz = freqb + (size_t)(256 + k) * 256;
#pragma unroll
    for (int mt = 0; mt < 2; mt++)
#pragma unroll
        for (int j = 0; j < 4; j++)
#pragma unroll
            for (int r = 0; r < 4; r++) {
                const int b = wm * 32 + mt * 16 + (l >> 2) + (r >> 1) * 8;
                const int v = v0 + wn * 32 + j * 8 + (l & 3) * 2 + (r & 1);
                const float o = hsig(acc_o[mt][j][r] + __ldg(bo + v));
                const float zz = o * tanhf(acc_z[mt][j][r] + __ldg(bz + v));
                atomicAdd(&z_out[b * 256 + v], zz);
            }
}

// ============================================================================
// launch
// ============================================================================
extern "C" void kernel_launch(void* const* d_in, const int* in_sizes, int n_in,
                              void* d_out, int out_size)
{
    const float* x        = (const float*)d_in[0];
    const float* t        = (const float*)d_in[1];
    const float* z_prev   = (const float*)d_in[2];
    const float* Im_prev  = (const float*)d_in[3];
    const float* Re_prev  = (const float*)d_in[4];
    const float* omg_prev = (const float*)d_in[5];
    const float* kern     = (const float*)d_in[6];
    const float* recur    = (const float*)d_in[7];
    const float* freq_k   = (const float*)d_in[8];
    const float* freq_ki  = (const float*)d_in[9];
    const float* bias     = (const float*)d_in[10];
    const float* freqb    = (const float*)d_in[11];

    float* out     = (float*)d_out;
    float* z_out   = out;
    float* im_out  = out + 32768;
    float* re_out  = out + 32768 + 8388608;
    float* omg_out = out + 32768 + 2 * 8388608;

    static int smem_set = 0;
    if (!smem_set) {
        cudaFuncSetAttribute(k_freq_mma, cudaFuncAttributeMaxDynamicSharedMemorySize, SMEM_TOT);
        smem_set = 1;
    }

    k_gates_gemm<<<dim3(20, 4, 2), 256>>>(x, z_prev, kern, recur, z_out);
    k_reim<<<dim3(4, 4, 128), 256>>>(Re_prev, Im_prev, omg_prev, t, bias, im_out, re_out, omg_out);
    k_freq_mma<<<dim3(4, 256), 256, SMEM_TOT>>>(freq_k, freq_ki, freqb, z_out);
}